// round 7
// baseline (speedup 1.0000x reference)
#include <cuda_runtime.h>
#include <cuda_fp16.h>
#include <cstdint>

// out[i,j] = exp(-(||H1_i||^2 + ||H2_j||^2 - 2*H1_i.H2_j)),  H1,H2: [8192,64] f32.
//
// Round 7: R6 (smem-staged coalesced epilogue) with the phase-2 loop bound
// fixed: 128 rows x 32 float4 = 4096 chunks per CTA -> 16 iterations of 256
// threads (R6 ran 8 and left rows 64..127 unwritten).

#define NR    8192
#define KDIM  64
#define TM    128
#define TN    128
#define LOG2E 1.4426950408889634f
#define SSTR  132      // stage row stride in floats (128 + 4 pad)

// ---- device scratch: fp16 row images, 128-row blocks of 16KB, pre-swizzled ----
__device__ __align__(1024) uint8_t g_H1s[(size_t)NR * 128];
__device__ __align__(1024) uint8_t g_H2s[(size_t)NR * 128];
__device__ float g_norm1[NR];
__device__ float g_norm2[NR];

// ============================ PTX helpers ============================
__device__ __forceinline__ uint32_t smem_u32(const void* p) {
    uint32_t a;
    asm("{ .reg .u64 t; cvta.to.shared.u64 t, %1; cvt.u32.u64 %0, t; }" : "=r"(a) : "l"(p));
    return a;
}
__device__ __forceinline__ float ex2f(float x) {
    float y; asm("ex2.approx.ftz.f32 %0, %1;" : "=f"(y) : "f"(x)); return y;
}
__device__ __forceinline__ void ldsm_x4(uint32_t& r0, uint32_t& r1, uint32_t& r2, uint32_t& r3,
                                        uint32_t addr) {
    asm volatile("ldmatrix.sync.aligned.m8n8.x4.shared.b16 {%0,%1,%2,%3}, [%4];"
                 : "=r"(r0), "=r"(r1), "=r"(r2), "=r"(r3) : "r"(addr));
}
__device__ __forceinline__ void mma16816(float& c0, float& c1, float& c2, float& c3,
                                         uint32_t a0, uint32_t a1, uint32_t a2, uint32_t a3,
                                         uint32_t b0, uint32_t b1) {
    asm volatile(
        "mma.sync.aligned.m16n8k16.row.col.f32.f16.f16.f32 "
        "{%0,%1,%2,%3}, {%4,%5,%6,%7}, {%8,%9}, {%0,%1,%2,%3};"
        : "+f"(c0), "+f"(c1), "+f"(c2), "+f"(c3)
        : "r"(a0), "r"(a1), "r"(a2), "r"(a3), "r"(b0), "r"(b1));
}
#define CP_ASYNC16(dst, src) \
    asm volatile("cp.async.cg.shared.global [%0], [%1], 16;" :: "r"(dst), "l"(src))
#define CP_ASYNC_COMMIT()  asm volatile("cp.async.commit_group;" ::: "memory")
#define CP_ASYNC_WAIT0()   asm volatile("cp.async.wait_group 0;" ::: "memory")

// ============================ pre-kernel ============================
__global__ void prep_kernel(const float* __restrict__ H1, const float* __restrict__ H2, int n1) {
    int gid = blockIdx.x * blockDim.x + threadIdx.x;
    int row = gid >> 4;
    int q   = gid & 15;                 // float4 chunk: k = 4q..4q+3
    bool isA = row < n1;
    int r = isA ? row : row - n1;
    const float* src = isA ? H1 : H2;
    float4 v = reinterpret_cast<const float4*>(src)[(size_t)r * 16 + q];

    float x[4] = {v.x, v.y, v.z, v.w};
    uint32_t hu[4];
    float ss = 0.f;
    #pragma unroll
    for (int e = 0; e < 4; e++) {
        hu[e] = (uint32_t)__half_as_ushort(__float2half_rn(x[e]));
        ss = fmaf(x[e], x[e], ss);
    }
    uint2 hi = make_uint2(hu[0] | (hu[1] << 16), hu[2] | (hu[3] << 16));

    int ib = r >> 7, lr = r & 127;
    int chunk = q >> 1;
    int swc = chunk ^ (lr & 7);               // XOR swizzle for ldmatrix
    size_t off = (size_t)ib * 16384 + (size_t)lr * 128 + swc * 16 + (q & 1) * 8;
    uint8_t* base = isA ? g_H1s : g_H2s;
    *reinterpret_cast<uint2*>(base + off) = hi;

    #pragma unroll
    for (int o = 8; o; o >>= 1) ss += __shfl_xor_sync(0xffffffffu, ss, o, 16);
    if (q == 0) (isA ? g_norm1 : g_norm2)[r] = ss;
}

// ============================ main kernel ============================
// smem: norms [0,1024) | A tile [1024,17408) | B tile [17408,33792)
// stage (overlays A/B after mainloop): [1024, 1024 + 128*SSTR*4)
#define SM_N1    0
#define SM_N2    512
#define SM_A     1024
#define SM_B     (1024 + 16384)
#define SM_STAGE 1024
#define SM_TOT   (1024 + 128 * SSTR * 4)   // 68608 B

__global__ __launch_bounds__(256, 2) void gk_mma(float* __restrict__ out) {
    extern __shared__ uint8_t smem[];
    const uint32_t sb = smem_u32(smem);
    const int tid  = threadIdx.x;
    const int wid  = tid >> 5;
    const int lane = tid & 31;
    const int iT = blockIdx.y * TM;
    const int jT = blockIdx.x * TN;

    // ---- async copy of pre-swizzled tile images (16KB + 16KB) ----
    {
        const uint8_t* ga = g_H1s + (size_t)blockIdx.y * 16384;
        const uint8_t* gb = g_H2s + (size_t)blockIdx.x * 16384;
        #pragma unroll
        for (int s = 0; s < 4; s++) {
            uint32_t off = (uint32_t)(tid + s * 256) * 16;
            CP_ASYNC16(sb + SM_A + off, ga + off);
            CP_ASYNC16(sb + SM_B + off, gb + off);
        }
        CP_ASYNC_COMMIT();
        if (tid < 128) {
            ((float*)(smem + SM_N1))[tid] = g_norm1[iT + tid] * LOG2E;
            ((float*)(smem + SM_N2))[tid] = g_norm2[jT + tid] * LOG2E;
        }
        CP_ASYNC_WAIT0();
    }
    __syncthreads();

    // warp tile: 64 rows x 32 cols.  wr in {0,1}, wc in {0..3}
    const int wr = wid & 1;
    const int wc = wid >> 1;

    float acc[4][4][4];                 // [mi][ni][frag]
    #pragma unroll
    for (int i = 0; i < 4; i++)
        #pragma unroll
        for (int j = 0; j < 4; j++)
            #pragma unroll
            for (int f = 0; f < 4; f++) acc[i][j][f] = 0.f;

    // ldmatrix lane addressing
    uint32_t aRow[4], aXor[4], aKbit = (uint32_t)(lane >> 4);
    #pragma unroll
    for (int mi = 0; mi < 4; mi++) {
        int ra = wr * 64 + mi * 16 + (lane & 15);
        aRow[mi] = sb + SM_A + ra * 128;
        aXor[mi] = (uint32_t)(ra & 7);
    }
    uint32_t bRow[2], bXor[2], bKbit = (uint32_t)((lane >> 3) & 1);
    #pragma unroll
    for (int ng = 0; ng < 2; ng++) {
        int nb = wc * 32 + ng * 16 + (lane & 7) + ((lane >> 4) & 1) * 8;
        bRow[ng] = sb + SM_B + nb * 128;
        bXor[ng] = (uint32_t)(nb & 7);
    }

    // Single term: per kc, 4 A-LDSM + 2 B-LDSM -> 16 HMMA.
    #pragma unroll
    for (int kc = 0; kc < 4; kc++) {
        uint32_t aF[4][4], bF[2][4];
        #pragma unroll
        for (int mi = 0; mi < 4; mi++) {
            uint32_t ch = (2u * kc + aKbit) ^ aXor[mi];
            ldsm_x4(aF[mi][0], aF[mi][1], aF[mi][2], aF[mi][3], aRow[mi] + (ch << 4));
        }
        #pragma unroll
        for (int ng = 0; ng < 2; ng++) {
            uint32_t ch = (2u * kc + bKbit) ^ bXor[ng];
            ldsm_x4(bF[ng][0], bF[ng][1], bF[ng][2], bF[ng][3], bRow[ng] + (ch << 4));
        }
        #pragma unroll
        for (int mi = 0; mi < 4; mi++)
            #pragma unroll
            for (int ni = 0; ni < 4; ni++)
                mma16816(acc[mi][ni][0], acc[mi][ni][1], acc[mi][ni][2], acc[mi][ni][3],
                         aF[mi][0], aF[mi][1], aF[mi][2], aF[mi][3],
                         bF[ni >> 1][(ni & 1) * 2], bF[ni >> 1][(ni & 1) * 2 + 1]);
    }

    // ---- epilogue phase 1: exp2 + stage into smem (overlays A/B tiles) ----
    const float* n1c = (const float*)(smem + SM_N1);
    const float* n2c = (const float*)(smem + SM_N2);
    const int rsub = lane >> 2;
    const int csub = (lane & 3) * 2;

    __syncthreads();                       // all LDSM done before overwrite
    float* stage = (float*)(smem + SM_STAGE);

    #pragma unroll
    for (int mi = 0; mi < 4; mi++) {
        int lr0 = wr * 64 + mi * 16 + rsub;
        float rn0 = n1c[lr0];
        float rn1 = n1c[lr0 + 8];
        #pragma unroll
        for (int ni = 0; ni < 4; ni++) {
            int lc = wc * 32 + ni * 8 + csub;
            float cn0 = n2c[lc], cn1 = n2c[lc + 1];
            float2 v0, v1;
            v0.x = ex2f(fmaf(acc[mi][ni][0], 2.f * LOG2E, -rn0) - cn0);
            v0.y = ex2f(fmaf(acc[mi][ni][1], 2.f * LOG2E, -rn0) - cn1);
            v1.x = ex2f(fmaf(acc[mi][ni][2], 2.f * LOG2E, -rn1) - cn0);
            v1.y = ex2f(fmaf(acc[mi][ni][3], 2.f * LOG2E, -rn1) - cn1);
            *reinterpret_cast<float2*>(stage + lr0 * SSTR + lc)       = v0;
            *reinterpret_cast<float2*>(stage + (lr0 + 8) * SSTR + lc) = v1;
        }
    }
    __syncthreads();

    // ---- epilogue phase 2: row-linear coalesced streaming stores ----
    // 128 rows x 32 float4 = 4096 chunks; 256 threads -> 16 iterations.
    #pragma unroll
    for (int it = 0; it < 16; it++) {
        int m  = it * 256 + tid;           // float4 chunk index within tile
        int r  = m >> 5;                   // tile row (32 float4 per row)
        int c4 = m & 31;
        float4 v = *reinterpret_cast<const float4*>(stage + r * SSTR + c4 * 4);
        __stcs(reinterpret_cast<float4*>(out + (size_t)(iT + r) * NR + jT) + c4, v);
    }
}

// ============================ launch ============================
extern "C" void kernel_launch(void* const* d_in, const int* in_sizes, int n_in,
                              void* d_out, int out_size)
{
    const float* H1 = (const float*)d_in[0];
    const float* H2 = (const float*)d_in[1];
    float* out = (float*)d_out;

    int n1 = in_sizes[0] / KDIM;   // 8192
    int n2 = in_sizes[1] / KDIM;   // 8192

    prep_kernel<<<(n1 + n2) * 16 / 256, 256>>>(H1, H2, n1);

    static bool attr_set = false;
    if (!attr_set) {
        cudaFuncSetAttribute(gk_mma, cudaFuncAttributeMaxDynamicSharedMemorySize, SM_TOT);
        attr_set = true;
    }
    dim3 grid(n2 / TN, n1 / TM);   // (64, 64)
    gk_mma<<<grid, 256, SM_TOT>>>(out);
}

// round 8
// speedup vs baseline: 1.3333x; 1.3333x over previous
#include <cuda_runtime.h>
#include <cuda_fp16.h>
#include <cstdint>

// out[i,j] = exp(-(||H1_i||^2 + ||H2_j||^2 - 2*H1_i.H2_j)),  H1,H2: [8192,64] f32.
//
// Round 8: R5 mainloop (fp16 single-term mma.sync) + shuffle-paired epilogue:
// one shfl.xor(1) exchange per fragment pair turns per-lane float2 stores into
// per-lane float4 stores (same 8 wavefronts per STG inst, 2x the bytes), with
// no smem staging and no barriers (R7's mistake).

#define NR    8192
#define KDIM  64
#define TM    128
#define TN    128
#define LOG2E 1.4426950408889634f

// ---- device scratch: fp16 row images, 128-row blocks of 16KB, pre-swizzled ----
__device__ __align__(1024) uint8_t g_H1s[(size_t)NR * 128];
__device__ __align__(1024) uint8_t g_H2s[(size_t)NR * 128];
__device__ float g_norm1[NR];
__device__ float g_norm2[NR];

// ============================ PTX helpers ============================
__device__ __forceinline__ uint32_t smem_u32(const void* p) {
    uint32_t a;
    asm("{ .reg .u64 t; cvta.to.shared.u64 t, %1; cvt.u32.u64 %0, t; }" : "=r"(a) : "l"(p));
    return a;
}
__device__ __forceinline__ float ex2f(float x) {
    float y; asm("ex2.approx.ftz.f32 %0, %1;" : "=f"(y) : "f"(x)); return y;
}
__device__ __forceinline__ void ldsm_x4(uint32_t& r0, uint32_t& r1, uint32_t& r2, uint32_t& r3,
                                        uint32_t addr) {
    asm volatile("ldmatrix.sync.aligned.m8n8.x4.shared.b16 {%0,%1,%2,%3}, [%4];"
                 : "=r"(r0), "=r"(r1), "=r"(r2), "=r"(r3) : "r"(addr));
}
__device__ __forceinline__ void mma16816(float& c0, float& c1, float& c2, float& c3,
                                         uint32_t a0, uint32_t a1, uint32_t a2, uint32_t a3,
                                         uint32_t b0, uint32_t b1) {
    asm volatile(
        "mma.sync.aligned.m16n8k16.row.col.f32.f16.f16.f32 "
        "{%0,%1,%2,%3}, {%4,%5,%6,%7}, {%8,%9}, {%0,%1,%2,%3};"
        : "+f"(c0), "+f"(c1), "+f"(c2), "+f"(c3)
        : "r"(a0), "r"(a1), "r"(a2), "r"(a3), "r"(b0), "r"(b1));
}
#define CP_ASYNC16(dst, src) \
    asm volatile("cp.async.cg.shared.global [%0], [%1], 16;" :: "r"(dst), "l"(src))
#define CP_ASYNC_COMMIT()  asm volatile("cp.async.commit_group;" ::: "memory")
#define CP_ASYNC_WAIT0()   asm volatile("cp.async.wait_group 0;" ::: "memory")

// ============================ pre-kernel ============================
__global__ void prep_kernel(const float* __restrict__ H1, const float* __restrict__ H2, int n1) {
    int gid = blockIdx.x * blockDim.x + threadIdx.x;
    int row = gid >> 4;
    int q   = gid & 15;                 // float4 chunk: k = 4q..4q+3
    bool isA = row < n1;
    int r = isA ? row : row - n1;
    const float* src = isA ? H1 : H2;
    float4 v = reinterpret_cast<const float4*>(src)[(size_t)r * 16 + q];

    float x[4] = {v.x, v.y, v.z, v.w};
    uint32_t hu[4];
    float ss = 0.f;
    #pragma unroll
    for (int e = 0; e < 4; e++) {
        hu[e] = (uint32_t)__half_as_ushort(__float2half_rn(x[e]));
        ss = fmaf(x[e], x[e], ss);
    }
    uint2 hi = make_uint2(hu[0] | (hu[1] << 16), hu[2] | (hu[3] << 16));

    int ib = r >> 7, lr = r & 127;
    int chunk = q >> 1;
    int swc = chunk ^ (lr & 7);               // XOR swizzle for ldmatrix
    size_t off = (size_t)ib * 16384 + (size_t)lr * 128 + swc * 16 + (q & 1) * 8;
    uint8_t* base = isA ? g_H1s : g_H2s;
    *reinterpret_cast<uint2*>(base + off) = hi;

    #pragma unroll
    for (int o = 8; o; o >>= 1) ss += __shfl_xor_sync(0xffffffffu, ss, o, 16);
    if (q == 0) (isA ? g_norm1 : g_norm2)[r] = ss;
}

// ============================ main kernel ============================
#define SM_A    0
#define SM_B    16384
#define SM_N1   32768
#define SM_N2   33280
#define SM_TOT  33792

__global__ __launch_bounds__(256, 2) void gk_mma(float* __restrict__ out) {
    extern __shared__ uint8_t smem[];
    const uint32_t sb = smem_u32(smem);
    const int tid  = threadIdx.x;
    const int wid  = tid >> 5;
    const int lane = tid & 31;
    const int iT = blockIdx.y * TM;
    const int jT = blockIdx.x * TN;

    // ---- async copy of pre-swizzled tile images (16KB + 16KB) ----
    {
        const uint8_t* ga = g_H1s + (size_t)blockIdx.y * 16384;
        const uint8_t* gb = g_H2s + (size_t)blockIdx.x * 16384;
        #pragma unroll
        for (int s = 0; s < 4; s++) {
            uint32_t off = (uint32_t)(tid + s * 256) * 16;
            CP_ASYNC16(sb + SM_A + off, ga + off);
            CP_ASYNC16(sb + SM_B + off, gb + off);
        }
        CP_ASYNC_COMMIT();
        if (tid < 128) {
            ((float*)(smem + SM_N1))[tid] = g_norm1[iT + tid] * LOG2E;
            ((float*)(smem + SM_N2))[tid] = g_norm2[jT + tid] * LOG2E;
        }
        CP_ASYNC_WAIT0();
    }
    __syncthreads();

    // warp tile: 64 rows x 32 cols.  wr in {0,1}, wc in {0..3}
    const int wr = wid & 1;
    const int wc = wid >> 1;

    float acc[4][4][4];                 // [mi][ni][frag]
    #pragma unroll
    for (int i = 0; i < 4; i++)
        #pragma unroll
        for (int j = 0; j < 4; j++)
            #pragma unroll
            for (int f = 0; f < 4; f++) acc[i][j][f] = 0.f;

    // ldmatrix lane addressing
    uint32_t aRow[4], aXor[4], aKbit = (uint32_t)(lane >> 4);
    #pragma unroll
    for (int mi = 0; mi < 4; mi++) {
        int ra = wr * 64 + mi * 16 + (lane & 15);
        aRow[mi] = sb + SM_A + ra * 128;
        aXor[mi] = (uint32_t)(ra & 7);
    }
    uint32_t bRow[2], bXor[2], bKbit = (uint32_t)((lane >> 3) & 1);
    #pragma unroll
    for (int ng = 0; ng < 2; ng++) {
        int nb = wc * 32 + ng * 16 + (lane & 7) + ((lane >> 4) & 1) * 8;
        bRow[ng] = sb + SM_B + nb * 128;
        bXor[ng] = (uint32_t)(nb & 7);
    }

    // Single term: per kc, 4 A-LDSM + 2 B-LDSM -> 16 HMMA.
    #pragma unroll
    for (int kc = 0; kc < 4; kc++) {
        uint32_t aF[4][4], bF[2][4];
        #pragma unroll
        for (int mi = 0; mi < 4; mi++) {
            uint32_t ch = (2u * kc + aKbit) ^ aXor[mi];
            ldsm_x4(aF[mi][0], aF[mi][1], aF[mi][2], aF[mi][3], aRow[mi] + (ch << 4));
        }
        #pragma unroll
        for (int ng = 0; ng < 2; ng++) {
            uint32_t ch = (2u * kc + bKbit) ^ bXor[ng];
            ldsm_x4(bF[ng][0], bF[ng][1], bF[ng][2], bF[ng][3], bRow[ng] + (ch << 4));
        }
        #pragma unroll
        for (int mi = 0; mi < 4; mi++)
            #pragma unroll
            for (int ni = 0; ni < 4; ni++)
                mma16816(acc[mi][ni][0], acc[mi][ni][1], acc[mi][ni][2], acc[mi][ni][3],
                         aF[mi][0], aF[mi][1], aF[mi][2], aF[mi][3],
                         bF[ni >> 1][(ni & 1) * 2], bF[ni >> 1][(ni & 1) * 2 + 1]);
    }

    // ---- epilogue: exp2, then shfl.xor(1) pairing -> float4 streaming stores ----
    const float* n1c = (const float*)(smem + SM_N1);
    const float* n2c = (const float*)(smem + SM_N2);
    const int t  = lane & 3;            // column sub-id
    const int g  = lane >> 2;           // row sub-id
    const bool odd = (t & 1);
    // store column base for this lane's float4s
    const int colb = wc * 32 + (t & 1) * 16 + (t >> 1) * 4;

    #pragma unroll
    for (int mi = 0; mi < 4; mi++) {
        int lr0 = wr * 64 + mi * 16 + g;
        float rnA = n1c[lr0];
        float rnB = n1c[lr0 + 8];
        float2 cn[4];
        #pragma unroll
        for (int ni = 0; ni < 4; ni++)
            cn[ni] = *reinterpret_cast<const float2*>(&n2c[wc * 32 + ni * 8 + 2 * t]);

        #pragma unroll
        for (int half = 0; half < 2; half++) {
            float rn = half ? rnB : rnA;
            float2 f[4];
            #pragma unroll
            for (int ni = 0; ni < 4; ni++) {
                f[ni].x = ex2f(fmaf(acc[mi][ni][half * 2 + 0], 2.f * LOG2E, -rn) - cn[ni].x);
                f[ni].y = ex2f(fmaf(acc[mi][ni][half * 2 + 1], 2.f * LOG2E, -rn) - cn[ni].y);
            }
            // exchange with xor-1 partner: even lanes end up with frag{0,1},
            // odd lanes with frag{2,3}, each as full float4s.
            float2 v0 = odd ? f[0] : f[2];
            float2 v1 = odd ? f[1] : f[3];
            float2 r0, r1;
            r0.x = __shfl_xor_sync(0xffffffffu, v0.x, 1);
            r0.y = __shfl_xor_sync(0xffffffffu, v0.y, 1);
            r1.x = __shfl_xor_sync(0xffffffffu, v1.x, 1);
            r1.y = __shfl_xor_sync(0xffffffffu, v1.y, 1);
            float4 w0 = odd ? make_float4(r0.x, r0.y, f[2].x, f[2].y)
                            : make_float4(f[0].x, f[0].y, r0.x, r0.y);
            float4 w1 = odd ? make_float4(r1.x, r1.y, f[3].x, f[3].y)
                            : make_float4(f[1].x, f[1].y, r1.x, r1.y);
            float* p = out + (size_t)(iT + lr0 + half * 8) * NR + jT + colb;
            __stcs(reinterpret_cast<float4*>(p), w0);
            __stcs(reinterpret_cast<float4*>(p + 8), w1);
        }
    }
}

// ============================ launch ============================
extern "C" void kernel_launch(void* const* d_in, const int* in_sizes, int n_in,
                              void* d_out, int out_size)
{
    const float* H1 = (const float*)d_in[0];
    const float* H2 = (const float*)d_in[1];
    float* out = (float*)d_out;

    int n1 = in_sizes[0] / KDIM;   // 8192
    int n2 = in_sizes[1] / KDIM;   // 8192

    prep_kernel<<<(n1 + n2) * 16 / 256, 256>>>(H1, H2, n1);

    static bool attr_set = false;
    if (!attr_set) {
        cudaFuncSetAttribute(gk_mma, cudaFuncAttributeMaxDynamicSharedMemorySize, SM_TOT);
        attr_set = true;
    }
    dim3 grid(n2 / TN, n1 / TM);   // (64, 64)
    gk_mma<<<grid, 256, SM_TOT>>>(out);
}

// round 9
// speedup vs baseline: 1.3793x; 1.0345x over previous
#include <cuda_runtime.h>
#include <cuda_fp16.h>
#include <cstdint>

// out[i,j] = exp(-(||H1_i||^2 + ||H2_j||^2 - 2*H1_i.H2_j)),  H1,H2: [8192,64] f32.
//
// Round 9: R8 + second shuffle level. xor(1) merges col-pairs into float4;
// new xor(16) exchange of the upper float4 regroups lanes so each STG.128
// covers 4 complete 128B rows (4 wavefronts/inst, zero write waste).
// Store wavefronts per CTA: 1024 -> 512.

#define NR    8192
#define KDIM  64
#define TM    128
#define TN    128
#define LOG2E 1.4426950408889634f

// ---- device scratch: fp16 row images, 128-row blocks of 16KB, pre-swizzled ----
__device__ __align__(1024) uint8_t g_H1s[(size_t)NR * 128];
__device__ __align__(1024) uint8_t g_H2s[(size_t)NR * 128];
__device__ float g_norm1[NR];
__device__ float g_norm2[NR];

// ============================ PTX helpers ============================
__device__ __forceinline__ uint32_t smem_u32(const void* p) {
    uint32_t a;
    asm("{ .reg .u64 t; cvta.to.shared.u64 t, %1; cvt.u32.u64 %0, t; }" : "=r"(a) : "l"(p));
    return a;
}
__device__ __forceinline__ float ex2f(float x) {
    float y; asm("ex2.approx.ftz.f32 %0, %1;" : "=f"(y) : "f"(x)); return y;
}
__device__ __forceinline__ void ldsm_x4(uint32_t& r0, uint32_t& r1, uint32_t& r2, uint32_t& r3,
                                        uint32_t addr) {
    asm volatile("ldmatrix.sync.aligned.m8n8.x4.shared.b16 {%0,%1,%2,%3}, [%4];"
                 : "=r"(r0), "=r"(r1), "=r"(r2), "=r"(r3) : "r"(addr));
}
__device__ __forceinline__ void mma16816(float& c0, float& c1, float& c2, float& c3,
                                         uint32_t a0, uint32_t a1, uint32_t a2, uint32_t a3,
                                         uint32_t b0, uint32_t b1) {
    asm volatile(
        "mma.sync.aligned.m16n8k16.row.col.f32.f16.f16.f32 "
        "{%0,%1,%2,%3}, {%4,%5,%6,%7}, {%8,%9}, {%0,%1,%2,%3};"
        : "+f"(c0), "+f"(c1), "+f"(c2), "+f"(c3)
        : "r"(a0), "r"(a1), "r"(a2), "r"(a3), "r"(b0), "r"(b1));
}
#define CP_ASYNC16(dst, src) \
    asm volatile("cp.async.cg.shared.global [%0], [%1], 16;" :: "r"(dst), "l"(src))
#define CP_ASYNC_COMMIT()  asm volatile("cp.async.commit_group;" ::: "memory")
#define CP_ASYNC_WAIT0()   asm volatile("cp.async.wait_group 0;" ::: "memory")

// ============================ pre-kernel ============================
__global__ void prep_kernel(const float* __restrict__ H1, const float* __restrict__ H2, int n1) {
    int gid = blockIdx.x * blockDim.x + threadIdx.x;
    int row = gid >> 4;
    int q   = gid & 15;                 // float4 chunk: k = 4q..4q+3
    bool isA = row < n1;
    int r = isA ? row : row - n1;
    const float* src = isA ? H1 : H2;
    float4 v = reinterpret_cast<const float4*>(src)[(size_t)r * 16 + q];

    float x[4] = {v.x, v.y, v.z, v.w};
    uint32_t hu[4];
    float ss = 0.f;
    #pragma unroll
    for (int e = 0; e < 4; e++) {
        hu[e] = (uint32_t)__half_as_ushort(__float2half_rn(x[e]));
        ss = fmaf(x[e], x[e], ss);
    }
    uint2 hi = make_uint2(hu[0] | (hu[1] << 16), hu[2] | (hu[3] << 16));

    int ib = r >> 7, lr = r & 127;
    int chunk = q >> 1;
    int swc = chunk ^ (lr & 7);               // XOR swizzle for ldmatrix
    size_t off = (size_t)ib * 16384 + (size_t)lr * 128 + swc * 16 + (q & 1) * 8;
    uint8_t* base = isA ? g_H1s : g_H2s;
    *reinterpret_cast<uint2*>(base + off) = hi;

    #pragma unroll
    for (int o = 8; o; o >>= 1) ss += __shfl_xor_sync(0xffffffffu, ss, o, 16);
    if (q == 0) (isA ? g_norm1 : g_norm2)[r] = ss;
}

// ============================ main kernel ============================
#define SM_A    0
#define SM_B    16384
#define SM_N1   32768
#define SM_N2   33280
#define SM_TOT  33792

__global__ __launch_bounds__(256, 2) void gk_mma(float* __restrict__ out) {
    extern __shared__ uint8_t smem[];
    const uint32_t sb = smem_u32(smem);
    const int tid  = threadIdx.x;
    const int wid  = tid >> 5;
    const int lane = tid & 31;
    const int iT = blockIdx.y * TM;
    const int jT = blockIdx.x * TN;

    // ---- async copy of pre-swizzled tile images (16KB + 16KB) ----
    {
        const uint8_t* ga = g_H1s + (size_t)blockIdx.y * 16384;
        const uint8_t* gb = g_H2s + (size_t)blockIdx.x * 16384;
        #pragma unroll
        for (int s = 0; s < 4; s++) {
            uint32_t off = (uint32_t)(tid + s * 256) * 16;
            CP_ASYNC16(sb + SM_A + off, ga + off);
            CP_ASYNC16(sb + SM_B + off, gb + off);
        }
        CP_ASYNC_COMMIT();
        if (tid < 128) {
            ((float*)(smem + SM_N1))[tid] = g_norm1[iT + tid] * LOG2E;
            ((float*)(smem + SM_N2))[tid] = g_norm2[jT + tid] * LOG2E;
        }
        CP_ASYNC_WAIT0();
    }
    __syncthreads();

    // warp tile: 64 rows x 32 cols.  wr in {0,1}, wc in {0..3}
    const int wr = wid & 1;
    const int wc = wid >> 1;

    float acc[4][4][4];                 // [mi][ni][frag]
    #pragma unroll
    for (int i = 0; i < 4; i++)
        #pragma unroll
        for (int j = 0; j < 4; j++)
            #pragma unroll
            for (int f = 0; f < 4; f++) acc[i][j][f] = 0.f;

    // ldmatrix lane addressing
    uint32_t aRow[4], aXor[4], aKbit = (uint32_t)(lane >> 4);
    #pragma unroll
    for (int mi = 0; mi < 4; mi++) {
        int ra = wr * 64 + mi * 16 + (lane & 15);
        aRow[mi] = sb + SM_A + ra * 128;
        aXor[mi] = (uint32_t)(ra & 7);
    }
    uint32_t bRow[2], bXor[2], bKbit = (uint32_t)((lane >> 3) & 1);
    #pragma unroll
    for (int ng = 0; ng < 2; ng++) {
        int nb = wc * 32 + ng * 16 + (lane & 7) + ((lane >> 4) & 1) * 8;
        bRow[ng] = sb + SM_B + nb * 128;
        bXor[ng] = (uint32_t)(nb & 7);
    }

    // Single term: per kc, 4 A-LDSM + 2 B-LDSM -> 16 HMMA.
    #pragma unroll
    for (int kc = 0; kc < 4; kc++) {
        uint32_t aF[4][4], bF[2][4];
        #pragma unroll
        for (int mi = 0; mi < 4; mi++) {
            uint32_t ch = (2u * kc + aKbit) ^ aXor[mi];
            ldsm_x4(aF[mi][0], aF[mi][1], aF[mi][2], aF[mi][3], aRow[mi] + (ch << 4));
        }
        #pragma unroll
        for (int ng = 0; ng < 2; ng++) {
            uint32_t ch = (2u * kc + bKbit) ^ bXor[ng];
            ldsm_x4(bF[ng][0], bF[ng][1], bF[ng][2], bF[ng][3], bRow[ng] + (ch << 4));
        }
        #pragma unroll
        for (int mi = 0; mi < 4; mi++)
            #pragma unroll
            for (int ni = 0; ni < 4; ni++)
                mma16816(acc[mi][ni][0], acc[mi][ni][1], acc[mi][ni][2], acc[mi][ni][3],
                         aF[mi][0], aF[mi][1], aF[mi][2], aF[mi][3],
                         bF[ni >> 1][(ni & 1) * 2], bF[ni >> 1][(ni & 1) * 2 + 1]);
    }

    // ---- epilogue: exp2, xor(1) pairing -> float4, xor(16) row-merge -> 4wf STGs ----
    const float* n1c = (const float*)(smem + SM_N1);
    const float* n2c = (const float*)(smem + SM_N2);
    const int t  = lane & 3;            // column sub-id
    const int g  = lane >> 2;           // row sub-id 0..7
    const bool odd  = (t & 1);
    const bool hi_g = (g >= 4);
    const int  gl   = g & 3;
    const int colb = wc * 32 + (t & 1) * 16 + (t >> 1) * 4;

    #pragma unroll
    for (int mi = 0; mi < 4; mi++) {
        int lr0 = wr * 64 + mi * 16 + g;
        float rnA = n1c[lr0];
        float rnB = n1c[lr0 + 8];
        float2 cn[4];
        #pragma unroll
        for (int ni = 0; ni < 4; ni++)
            cn[ni] = *reinterpret_cast<const float2*>(&n2c[wc * 32 + ni * 8 + 2 * t]);

        #pragma unroll
        for (int half = 0; half < 2; half++) {
            float rn = half ? rnB : rnA;
            float2 f[4];
            #pragma unroll
            for (int ni = 0; ni < 4; ni++) {
                f[ni].x = ex2f(fmaf(acc[mi][ni][half * 2 + 0], 2.f * LOG2E, -rn) - cn[ni].x);
                f[ni].y = ex2f(fmaf(acc[mi][ni][half * 2 + 1], 2.f * LOG2E, -rn) - cn[ni].y);
            }
            // xor(1): even lanes end with frag{0,1} (cols colb..), odd with frag{2,3}
            float2 v0 = odd ? f[0] : f[2];
            float2 v1 = odd ? f[1] : f[3];
            float2 r0, r1;
            r0.x = __shfl_xor_sync(0xffffffffu, v0.x, 1);
            r0.y = __shfl_xor_sync(0xffffffffu, v0.y, 1);
            r1.x = __shfl_xor_sync(0xffffffffu, v1.x, 1);
            r1.y = __shfl_xor_sync(0xffffffffu, v1.y, 1);
            float4 w0 = odd ? make_float4(r0.x, r0.y, f[2].x, f[2].y)
                            : make_float4(f[0].x, f[0].y, r0.x, r0.y);
            float4 w1 = odd ? make_float4(r1.x, r1.y, f[3].x, f[3].y)
                            : make_float4(f[1].x, f[1].y, r1.x, r1.y);
            // xor(16): swap w1 between g and g^4 partners so each STG covers
            // 4 complete 128B rows.
            float4 w1x;
            w1x.x = __shfl_xor_sync(0xffffffffu, w1.x, 16);
            w1x.y = __shfl_xor_sync(0xffffffffu, w1.y, 16);
            w1x.z = __shfl_xor_sync(0xffffffffu, w1.z, 16);
            w1x.w = __shfl_xor_sync(0xffffffffu, w1.w, 16);

            const int Rbase = iT + wr * 64 + mi * 16 + half * 8;
            // inst1: rows Rbase..Rbase+3
            {
                float4 v = hi_g ? w1x : w0;
                int col = colb + (hi_g ? 8 : 0);
                __stcs(reinterpret_cast<float4*>(out + (size_t)(Rbase + gl) * NR + jT + col), v);
            }
            // inst2: rows Rbase+4..Rbase+7
            {
                float4 v = hi_g ? w0 : w1x;
                int col = colb + (hi_g ? 0 : 8);
                __stcs(reinterpret_cast<float4*>(out + (size_t)(Rbase + gl + 4) * NR + jT + col), v);
            }
        }
    }
}

// ============================ launch ============================
extern "C" void kernel_launch(void* const* d_in, const int* in_sizes, int n_in,
                              void* d_out, int out_size)
{
    const float* H1 = (const float*)d_in[0];
    const float* H2 = (const float*)d_in[1];
    float* out = (float*)d_out;

    int n1 = in_sizes[0] / KDIM;   // 8192
    int n2 = in_sizes[1] / KDIM;   // 8192

    prep_kernel<<<(n1 + n2) * 16 / 256, 256>>>(H1, H2, n1);

    static bool attr_set = false;
    if (!attr_set) {
        cudaFuncSetAttribute(gk_mma, cudaFuncAttributeMaxDynamicSharedMemorySize, SM_TOT);
        attr_set = true;
    }
    dim3 grid(n2 / TN, n1 / TM);   // (64, 64)
    gk_mma<<<grid, 256, SM_TOT>>>(out);
}